// round 1
// baseline (speedup 1.0000x reference)
#include <cuda_runtime.h>
#include <cuda_bf16.h>

// Shapes (fixed for this problem):
//  x     [16, 64, 64, 64]  f32  (NCHW)
//  W_off [18, 64, 3, 3]
//  b_off [18]
//  W_k   [128, 64, 3, 3]
//  b_k   [128]
//  out   [16, 128, 64, 64]

#define BB 16
#define CC 64
#define HH 64
#define WW 64
#define OCC 128
#define NOFF 18   // 2*9

// ---------------- scratch (device globals; no allocations) ----------------
__device__ float g_xt[BB * HH * WW * CC];        // NHWC transpose of x
__device__ float g_off[BB * NOFF * HH * WW];     // offsets, planar [b][18][h][w]
__device__ float g_wt[9 * CC * OCC];             // W_k transposed: [n][c][oc]

// ---------------- kernel A: NCHW -> NHWC transpose ----------------
__global__ __launch_bounds__(256) void k_tr(const float* __restrict__ x) {
    __shared__ float tile[64][65];
    int b = blockIdx.y, y = blockIdx.x;
    int tid = threadIdx.x;
    int lo = tid & 63, hi = tid >> 6;  // lo: 0..63, hi: 0..3
#pragma unroll
    for (int rep = 0; rep < 16; rep++) {
        int c = rep * 4 + hi;
        tile[c][lo] = x[((b * CC + c) * HH + y) * WW + lo];  // coalesced read along w
    }
    __syncthreads();
#pragma unroll
    for (int rep = 0; rep < 16; rep++) {
        int xcol = rep * 4 + hi;
        // coalesced write along c
        g_xt[((b * HH + y) * WW + xcol) * CC + lo] = tile[lo][xcol];
    }
}

// ---------------- kernel B: offset conv (3x3, 64 -> 18, pad 1) ----------------
// block: 256 threads = 4 thread-rows x 64 cols; each thread computes 2 vertical
// pixels x 18 outputs. Weights staged in smem as ws[c][tap][20] (padded for LDS.128).
__global__ __launch_bounds__(256) void k_off(const float* __restrict__ x,
                                             const float* __restrict__ Woff,
                                             const float* __restrict__ boff) {
    __shared__ float ws[64][9][20];  // 46080 B
    int b = blockIdx.y, rg = blockIdx.x;  // 8 row-groups of 8 rows
    int tid = threadIdx.x;
    int j = tid & 63, tr = tid >> 6;      // tr: 0..3
    int r0 = rg * 8 + tr * 2;             // rows r0, r0+1

    for (int t = tid; t < 64 * 9 * 18; t += 256) {
        int o = t % 18;
        int tap = (t / 18) % 9;
        int c = t / (18 * 9);
        ws[c][tap][o] = Woff[(o * CC + c) * 9 + tap];
    }

    float acc0[18], acc1[18];
#pragma unroll
    for (int o = 0; o < 18; o++) {
        float bv = __ldg(&boff[o]);
        acc0[o] = bv;
        acc1[o] = bv;
    }
    __syncthreads();

    for (int c = 0; c < CC; ++c) {
        float xv[4][3];
        const float* xp = x + ((b * CC + c) * HH) * WW;
#pragma unroll
        for (int rr = 0; rr < 4; rr++) {
            int row = r0 - 1 + rr;
#pragma unroll
            for (int cc2 = 0; cc2 < 3; cc2++) {
                int col = j - 1 + cc2;
                bool ok = (row >= 0) && (row < HH) && (col >= 0) && (col < WW);
                xv[rr][cc2] = ok ? __ldg(&xp[row * WW + col]) : 0.f;
            }
        }
#pragma unroll
        for (int tap = 0; tap < 9; tap++) {
            int dy = tap / 3, dx = tap % 3;
            float xa = xv[dy][dx];
            float xb = xv[dy + 1][dx];
            const float* wp = &ws[c][tap][0];
#pragma unroll
            for (int o = 0; o < 18; o++) {
                float w = wp[o];
                acc0[o] += xa * w;
                acc1[o] += xb * w;
            }
        }
    }
    // planar store: g_off[((b*18+o)*64 + row)*64 + j]  (coalesced along j)
#pragma unroll
    for (int o = 0; o < 18; o++) {
        g_off[((b * NOFF + o) * HH + r0) * WW + j] = acc0[o];
        g_off[((b * NOFF + o) * HH + r0 + 1) * WW + j] = acc1[o];
    }
}

// ---------------- kernel C: W_k -> W_t[n][c][oc] ----------------
__global__ __launch_bounds__(256) void k_wt(const float* __restrict__ Wk) {
    int idx = blockIdx.x * 256 + threadIdx.x;
    if (idx < 9 * CC * OCC) {
        int oc = idx & 127;
        int c = (idx >> 7) & 63;
        int n = idx >> 13;
        g_wt[idx] = Wk[(oc * CC + c) * 9 + n];
    }
}

// ---------------- kernel D: fused bilinear sampling + output GEMM ----------------
// block = (b, row i). 64 pixels x 128 oc. 256 threads: tx(0..31)->oc=4tx,
// ty(0..7)->pixels 8ty..8ty+7. acc[4 oc][8 px].
__global__ __launch_bounds__(256) void k_main(const float* __restrict__ bk,
                                              float* __restrict__ out) {
    // smem: reused region — S_s[64][64] + W_s[32][128] during mainloop,
    // stage[128][65] during epilogue. 8320 floats.
    __shared__ float smem[8320];
    __shared__ float OFF[2][9][64];
    float* S_s = smem;         // [p][c]  4096
    float* W_s = smem + 4096;  // [k][oc] 4096

    int b = blockIdx.y, i = blockIdx.x;
    int tid = threadIdx.x;
    int tx = tid & 31;   // oc group
    int ty = tid >> 5;   // pixel group / warp id
    int p_base = ty * 8;

    // load offsets for this row: [2][9][64]
    for (int t = tid; t < NOFF * 64; t += 256) {
        int o = t >> 6;
        int j = t & 63;
        float v = g_off[((b * NOFF + o) * HH + i) * WW + j];
        if (o < 9) OFF[0][o][j] = v;
        else       OFF[1][o - 9][j] = v;
    }

    float acc[4][8];
#pragma unroll
    for (int a = 0; a < 4; a++)
#pragma unroll
        for (int p = 0; p < 8; p++) acc[a][p] = 0.f;

    for (int n = 0; n < 9; ++n) {
        __syncthreads();  // previous GEMM done reading smem (also covers OFF init)

        // ---- sampling: warp ty handles pixels p_base..p_base+7 ----
        {
            int dxk = n / 3 - 1;  // row (h) kernel offset
            int dyk = n % 3 - 1;  // col (w) kernel offset
#pragma unroll
            for (int it = 0; it < 8; it++) {
                int p = p_base + it;
                float ox = OFF[0][n][p];
                float oy = OFF[1][n][p];
                float pxf = (float)(i + dxk) + ox;
                float pyf = (float)(p + dyk) + oy;
                pxf = fminf(fmaxf(pxf, 0.f), 63.f);
                pyf = fminf(fmaxf(pyf, 0.f), 63.f);
                float fx = floorf(pxf), fy = floorf(pyf);
                int x0 = (int)fx, y0 = (int)fy;
                int x1 = min(x0 + 1, 63), y1 = min(y0 + 1, 63);
                float tfx = pxf - fx, tfy = pyf - fy;
                float w00 = (1.f - tfx) * (1.f - tfy);
                float w10 = tfx * (1.f - tfy);
                float w01 = (1.f - tfx) * tfy;
                float w11 = tfx * tfy;

                const float2* r00 = (const float2*)(g_xt + ((b * HH + x0) * WW + y0) * CC);
                const float2* r10 = (const float2*)(g_xt + ((b * HH + x1) * WW + y0) * CC);
                const float2* r01 = (const float2*)(g_xt + ((b * HH + x0) * WW + y1) * CC);
                const float2* r11 = (const float2*)(g_xt + ((b * HH + x1) * WW + y1) * CC);
                float2 a = __ldg(&r00[tx]);
                float2 bb = __ldg(&r10[tx]);
                float2 cc2 = __ldg(&r01[tx]);
                float2 dd = __ldg(&r11[tx]);
                float2 s;
                s.x = a.x * w00 + bb.x * w10 + cc2.x * w01 + dd.x * w11;
                s.y = a.y * w00 + bb.y * w10 + cc2.y * w01 + dd.y * w11;
                *(float2*)&S_s[p * 64 + 2 * tx] = s;
            }
        }

        // ---- two 32-wide k chunks ----
#pragma unroll
        for (int hk = 0; hk < 2; hk++) {
            int k0 = hk * 32;
            // cooperative W chunk load: W_s[k][oc], k in [k0, k0+32)
            {
                const float4* src = (const float4*)(g_wt + n * (CC * OCC) + k0 * OCC);
                float4* dst = (float4*)W_s;
#pragma unroll
                for (int v = 0; v < 4; v++) dst[v * 256 + tid] = src[v * 256 + tid];
            }
            __syncthreads();

#pragma unroll
            for (int k4 = 0; k4 < 32; k4 += 4) {
                float4 sv[8];
#pragma unroll
                for (int pi = 0; pi < 8; pi++)
                    sv[pi] = *(const float4*)&S_s[(p_base + pi) * 64 + k0 + k4];
#pragma unroll
                for (int kk = 0; kk < 4; kk++) {
                    float4 wv = *(const float4*)&W_s[(k4 + kk) * OCC + 4 * tx];
#pragma unroll
                    for (int pi = 0; pi < 8; pi++) {
                        float s = (kk == 0) ? sv[pi].x : (kk == 1) ? sv[pi].y
                                 : (kk == 2) ? sv[pi].z : sv[pi].w;
                        acc[0][pi] += wv.x * s;
                        acc[1][pi] += wv.y * s;
                        acc[2][pi] += wv.z * s;
                        acc[3][pi] += wv.w * s;
                    }
                }
            }
            __syncthreads();  // done reading W_s (and S_s on last chunk)
        }
    }

    // ---- epilogue: stage through smem for coalesced NCHW stores ----
    float* stage = smem;  // [128][65]
#pragma unroll
    for (int oi = 0; oi < 4; oi++)
#pragma unroll
        for (int pi = 0; pi < 8; pi++)
            stage[(4 * tx + oi) * 65 + p_base + pi] = acc[oi][pi];
    __syncthreads();
#pragma unroll
    for (int rep = 0; rep < 32; rep++) {
        int oc = rep * 4 + (tid >> 6);
        int j = tid & 63;
        out[((b * OCC + oc) * HH + i) * WW + j] = stage[oc * 65 + j] + __ldg(&bk[oc]);
    }
}

// ---------------- launch ----------------
extern "C" void kernel_launch(void* const* d_in, const int* in_sizes, int n_in,
                              void* d_out, int out_size) {
    const float* x = (const float*)d_in[0];
    const float* Woff = (const float*)d_in[1];
    const float* boff = (const float*)d_in[2];
    const float* Wk = (const float*)d_in[3];
    const float* bk = (const float*)d_in[4];
    float* out = (float*)d_out;

    k_tr<<<dim3(HH, BB), 256>>>(x);
    k_off<<<dim3(8, BB), 256>>>(x, Woff, boff);
    k_wt<<<dim3((9 * CC * OCC + 255) / 256), 256>>>(Wk);
    k_main<<<dim3(HH, BB), 256>>>(bk, out);
}

// round 3
// speedup vs baseline: 1.4242x; 1.4242x over previous
#include <cuda_runtime.h>
#include <cuda_bf16.h>
#include <cstdint>

// Shapes:
//  x [16,64,64,64] f32 NCHW, W_off [18,64,3,3], b_off[18], W_k [128,64,3,3], b_k[128]
//  out [16,128,64,64]

#define BB 16
#define CC 64
#define HH 64
#define WW 64
#define OCC 128
#define NOFF 18

// ---------------- scratch ----------------
__device__ float g_xt[BB * HH * WW * CC];          // NHWC x
__device__ float g_off[BB * NOFF * HH * WW];       // offsets planar
__device__ __nv_bfloat16 g_wb[9 * 2 * CC * OCC];   // [tap][hi/lo] 16KB tiles, [c][oc] pre-swizzled

// swizzles
#define SW128(o) ((o) ^ (((o) >> 3) & 0x70))   // 128B rows (A: [px][64c] bf16)
#define SWB(o)   ((o) ^ (((o) >> 4) & 0x70))   // 256B rows (B: [c][128oc] bf16)

__device__ __forceinline__ uint32_t smem_u32(const void* p) {
    uint32_t a;
    asm("{ .reg .u64 t; cvta.to.shared.u64 t, %1; cvt.u32.u64 %0, t; }" : "=r"(a) : "l"(p));
    return a;
}

__device__ __forceinline__ void ldmA(uint32_t* r, uint32_t base, int m0, int k0, int lane) {
    uint32_t off = (uint32_t)(m0 + (lane & 15)) * 128u + (uint32_t)(k0 + ((lane >> 4) & 1) * 8) * 2u;
    uint32_t addr = base + SW128(off);
    asm volatile("ldmatrix.sync.aligned.m8n8.x4.shared.b16 {%0,%1,%2,%3}, [%4];"
                 : "=r"(r[0]), "=r"(r[1]), "=r"(r[2]), "=r"(r[3]) : "r"(addr));
}
__device__ __forceinline__ void ldmB(uint32_t* r, uint32_t base, int n0, int k0, int lane) {
    uint32_t off = (uint32_t)(k0 + (lane & 15)) * 256u + (uint32_t)(n0 + ((lane >> 4) & 1) * 8) * 2u;
    uint32_t addr = base + SWB(off);
    asm volatile("ldmatrix.sync.aligned.m8n8.x4.trans.shared.b16 {%0,%1,%2,%3}, [%4];"
                 : "=r"(r[0]), "=r"(r[1]), "=r"(r[2]), "=r"(r[3]) : "r"(addr));
}
__device__ __forceinline__ void mma16816(float* c, const uint32_t* a, const uint32_t* b) {
    asm volatile("mma.sync.aligned.m16n8k16.row.col.f32.bf16.bf16.f32 "
                 "{%0,%1,%2,%3}, {%4,%5,%6,%7}, {%8,%9}, {%0,%1,%2,%3};"
                 : "+f"(c[0]), "+f"(c[1]), "+f"(c[2]), "+f"(c[3])
                 : "r"(a[0]), "r"(a[1]), "r"(a[2]), "r"(a[3]), "r"(b[0]), "r"(b[1]));
}

// ---------------- kernel A: NCHW -> NHWC transpose ----------------
__global__ __launch_bounds__(256) void k_tr(const float* __restrict__ x) {
    __shared__ float tile[64][65];
    int b = blockIdx.y, y = blockIdx.x;
    int tid = threadIdx.x;
    int lo = tid & 63, hi = tid >> 6;
#pragma unroll
    for (int rep = 0; rep < 16; rep++) {
        int c = rep * 4 + hi;
        tile[c][lo] = x[((b * CC + c) * HH + y) * WW + lo];
    }
    __syncthreads();
#pragma unroll
    for (int rep = 0; rep < 16; rep++) {
        int xcol = rep * 4 + hi;
        g_xt[((b * HH + y) * WW + xcol) * CC + lo] = tile[lo][xcol];
    }
}

// ---------------- kernel B: offset conv (3x3, 64 -> 18, pad 1) ----------------
__global__ __launch_bounds__(256) void k_off(const float* __restrict__ x,
                                             const float* __restrict__ Woff,
                                             const float* __restrict__ boff) {
    __shared__ float ws[64][9][20];
    int b = blockIdx.y, rg = blockIdx.x;
    int tid = threadIdx.x;
    int j = tid & 63, tr = tid >> 6;
    int r0 = rg * 8 + tr * 2;

    for (int t = tid; t < 64 * 9 * 18; t += 256) {
        int o = t % 18;
        int tap = (t / 18) % 9;
        int c = t / (18 * 9);
        ws[c][tap][o] = Woff[(o * CC + c) * 9 + tap];
    }

    float acc0[18], acc1[18];
#pragma unroll
    for (int o = 0; o < 18; o++) {
        float bv = __ldg(&boff[o]);
        acc0[o] = bv;
        acc1[o] = bv;
    }
    __syncthreads();

    for (int c = 0; c < CC; ++c) {
        float xv[4][3];
        const float* xp = x + ((b * CC + c) * HH) * WW;
#pragma unroll
        for (int rr = 0; rr < 4; rr++) {
            int row = r0 - 1 + rr;
#pragma unroll
            for (int cc2 = 0; cc2 < 3; cc2++) {
                int col = j - 1 + cc2;
                bool ok = (row >= 0) && (row < HH) && (col >= 0) && (col < WW);
                xv[rr][cc2] = ok ? __ldg(&xp[row * WW + col]) : 0.f;
            }
        }
#pragma unroll
        for (int tap = 0; tap < 9; tap++) {
            int dy = tap / 3, dx = tap % 3;
            float xa = xv[dy][dx];
            float xb = xv[dy + 1][dx];
            const float* wp = &ws[c][tap][0];
#pragma unroll
            for (int o = 0; o < 18; o++) {
                float w = wp[o];
                acc0[o] += xa * w;
                acc1[o] += xb * w;
            }
        }
    }
#pragma unroll
    for (int o = 0; o < 18; o++) {
        g_off[((b * NOFF + o) * HH + r0) * WW + j] = acc0[o];
        g_off[((b * NOFF + o) * HH + r0 + 1) * WW + j] = acc1[o];
    }
}

// ---------------- kernel C: W_k -> swizzled bf16 hi/lo [tap][hi/lo][c][oc] ----------------
__global__ __launch_bounds__(256) void k_wt(const float* __restrict__ Wk) {
    int idx = blockIdx.x * 256 + threadIdx.x;
    if (idx >= 9 * OCC * CC) return;
    int oc = idx & 127;
    int c = (idx >> 7) & 63;
    int n = idx >> 13;
    float v = Wk[(oc * CC + c) * 9 + n];
    __nv_bfloat16 hi = __float2bfloat16(v);
    __nv_bfloat16 lo = __float2bfloat16(v - __bfloat162float(hi));
    uint32_t off = (uint32_t)c * 256 + (uint32_t)oc * 2;  // byte offset within 16KB tile
    uint32_t sw = SWB(off);
    g_wb[(n * 2 + 0) * (CC * OCC) + sw / 2] = hi;
    g_wb[(n * 2 + 1) * (CC * OCC) + sw / 2] = lo;
}

// ---------------- kernel D: fused sampling + bf16-split HMMA GEMM ----------------
// block = (b, row-pair i0). M=128 px, N=128 oc, K=9 taps x 64 ch.
// warp grid 4(m) x 2(n): warp tile 32 px x 64 oc.
extern __shared__ char dsm_raw[];

__global__ __launch_bounds__(256, 2)
void k_main(const float* __restrict__ bk, float* __restrict__ out) {
    __shared__ float OFF[2][NOFF][64];

    int b = blockIdx.y, i0 = blockIdx.x * 2;
    int tid = threadIdx.x, wid = tid >> 5, lane = tid & 31;
    int mw = wid >> 1, nw = wid & 1;     // m-warp 0..3, n-warp 0..1
    int m0 = mw * 32, nbase = nw * 64;

    uint32_t raw = smem_u32(dsm_raw);
    uint32_t base = (raw + 2047) & ~2047u;   // 2KB align (SWB uses bits up to 10)
    char* abase = dsm_raw + (base - raw);
    uint32_t A_hi = base, A_lo = base + 16384;
    uint32_t B_hi = base + 32768, B_lo = base + 49152;

    // offsets for 2 rows
    for (int t = tid; t < 2 * NOFF * 64; t += 256) {
        int r = t / (NOFF * 64);
        int o = (t >> 6) % NOFF;
        int j = t & 63;
        OFF[r][o][j] = g_off[((b * NOFF + o) * HH + i0 + r) * WW + j];
    }
    __syncthreads();

    float acc[2][8][4];
#pragma unroll
    for (int mi = 0; mi < 2; mi++)
#pragma unroll
        for (int ni = 0; ni < 8; ni++)
#pragma unroll
            for (int q = 0; q < 4; q++) acc[mi][ni][q] = 0.f;

    for (int n = 0; n < 9; ++n) {
        if (n) __syncthreads();  // all warps done reading smem of prev tap

        // ---- B copy: 32KB linear (pre-swizzled hi|lo) ----
        {
            const float4* src = (const float4*)(g_wb + n * 2 * (CC * OCC));
            float4* dst = (float4*)(abase + 32768);
#pragma unroll
            for (int v = 0; v < 8; v++) dst[v * 256 + tid] = __ldg(&src[v * 256 + tid]);
        }

        // ---- sampling: warp wid -> 16 px; lane = channel pair ----
        {
            int dxk = n / 3 - 1, dyk = n % 3 - 1;
#pragma unroll 4
            for (int it = 0; it < 16; it++) {
                int p = wid * 16 + it;
                int r = p >> 6, j = p & 63;
                float ox = OFF[r][n][j];
                float oy = OFF[r][n + 9][j];
                float pxf = fminf(fmaxf((float)(i0 + r + dxk) + ox, 0.f), 63.f);
                float pyf = fminf(fmaxf((float)(j + dyk) + oy, 0.f), 63.f);
                float fx = floorf(pxf), fy = floorf(pyf);
                int x0 = (int)fx, y0 = (int)fy;
                int x1 = min(x0 + 1, 63), y1 = min(y0 + 1, 63);
                float tfx = pxf - fx, tfy = pyf - fy;
                float w00 = (1.f - tfx) * (1.f - tfy);
                float w10 = tfx * (1.f - tfy);
                float w01 = (1.f - tfx) * tfy;
                float w11 = tfx * tfy;

                const float2* r00 = (const float2*)(g_xt + ((b * HH + x0) * WW + y0) * CC) + lane;
                const float2* r10 = (const float2*)(g_xt + ((b * HH + x1) * WW + y0) * CC) + lane;
                const float2* r01 = (const float2*)(g_xt + ((b * HH + x0) * WW + y1) * CC) + lane;
                const float2* r11 = (const float2*)(g_xt + ((b * HH + x1) * WW + y1) * CC) + lane;
                float2 a = __ldg(r00), bb2 = __ldg(r10), cc2 = __ldg(r01), dd = __ldg(r11);
                float sx = a.x * w00 + bb2.x * w10 + cc2.x * w01 + dd.x * w11;
                float sy = a.y * w00 + bb2.y * w10 + cc2.y * w01 + dd.y * w11;

                __nv_bfloat16 hx = __float2bfloat16(sx);
                __nv_bfloat16 hy = __float2bfloat16(sy);
                __nv_bfloat162 hi2; hi2.x = hx; hi2.y = hy;
                __nv_bfloat162 lo2;
                lo2.x = __float2bfloat16(sx - __bfloat162float(hx));
                lo2.y = __float2bfloat16(sy - __bfloat162float(hy));

                uint32_t off = (uint32_t)p * 128 + (uint32_t)lane * 4;
                uint32_t sw = SW128(off);
                *(__nv_bfloat162*)(abase + sw) = hi2;
                *(__nv_bfloat162*)(abase + 16384 + sw) = lo2;
            }
        }
        __syncthreads();

        // ---- 4 k16 steps: hi*hi + lo*hi + hi*lo ----
#pragma unroll
        for (int ks = 0; ks < 4; ks++) {
            int k0 = ks * 16;
            uint32_t ah[8], al[8], bb[16];
            ldmA(ah + 0, A_hi, m0, k0, lane);
            ldmA(ah + 4, A_hi, m0 + 16, k0, lane);
            ldmA(al + 0, A_lo, m0, k0, lane);
            ldmA(al + 4, A_lo, m0 + 16, k0, lane);
#pragma unroll
            for (int g = 0; g < 4; g++) ldmB(bb + 4 * g, B_hi, nbase + 16 * g, k0, lane);
#pragma unroll
            for (int g = 0; g < 4; g++)
#pragma unroll
                for (int h = 0; h < 2; h++) {
                    const uint32_t* bf = bb + 4 * g + 2 * h;
                    mma16816(acc[0][2 * g + h], ah + 0, bf);
                    mma16816(acc[1][2 * g + h], ah + 4, bf);
                    mma16816(acc[0][2 * g + h], al + 0, bf);
                    mma16816(acc[1][2 * g + h], al + 4, bf);
                }
#pragma unroll
            for (int g = 0; g < 4; g++) ldmB(bb + 4 * g, B_lo, nbase + 16 * g, k0, lane);
#pragma unroll
            for (int g = 0; g < 4; g++)
#pragma unroll
                for (int h = 0; h < 2; h++) {
                    const uint32_t* bf = bb + 4 * g + 2 * h;
                    mma16816(acc[0][2 * g + h], ah + 0, bf);
                    mma16816(acc[1][2 * g + h], ah + 4, bf);
                }
        }
    }

    // ---- epilogue: direct stores (32B sectors) ----
    int gi = lane >> 2, t4 = lane & 3;
#pragma unroll
    for (int mi = 0; mi < 2; mi++) {
        int pr0 = m0 + mi * 16 + gi;
        int pr1 = pr0 + 8;
        int r0i = i0 + (pr0 >> 6), j0i = pr0 & 63;
        int r1i = i0 + (pr1 >> 6), j1i = pr1 & 63;
#pragma unroll
        for (int ni = 0; ni < 8; ni++) {
            int oc = nbase + ni * 8 + t4 * 2;
            float bv0 = __ldg(&bk[oc]), bv1 = __ldg(&bk[oc + 1]);
            out[((b * OCC + oc) * HH + r0i) * WW + j0i] = acc[mi][ni][0] + bv0;
            out[((b * OCC + oc + 1) * HH + r0i) * WW + j0i] = acc[mi][ni][1] + bv1;
            out[((b * OCC + oc) * HH + r1i) * WW + j1i] = acc[mi][ni][2] + bv0;
            out[((b * OCC + oc + 1) * HH + r1i) * WW + j1i] = acc[mi][ni][3] + bv1;
        }
    }
}

// ---------------- launch ----------------
extern "C" void kernel_launch(void* const* d_in, const int* in_sizes, int n_in,
                              void* d_out, int out_size) {
    const float* x = (const float*)d_in[0];
    const float* Woff = (const float*)d_in[1];
    const float* boff = (const float*)d_in[2];
    const float* Wk = (const float*)d_in[3];
    const float* bk = (const float*)d_in[4];
    float* out = (float*)d_out;

    k_tr<<<dim3(HH, BB), 256>>>(x);
    k_off<<<dim3(8, BB), 256>>>(x, Woff, boff);
    k_wt<<<dim3((9 * OCC * CC + 255) / 256), 256>>>(Wk);

    const int DSM = 65536 + 2048;
    cudaFuncSetAttribute(k_main, cudaFuncAttributeMaxDynamicSharedMemorySize, DSM);
    k_main<<<dim3(32, BB), 256, DSM>>>(bk, out);
}